// round 2
// baseline (speedup 1.0000x reference)
#include <cuda_runtime.h>
#include <cuda_bf16.h>
#include <mma.h>
#include <math.h>

using namespace nvcuda;

#define TSTEPS 512
#define BATCH  64
#define NIN    512
#define NH     1024
#define NBLK_P 96
#define WLD    1040      // bf16 elems per W-plane row (1024 + 16 pad)
#define ALD    136       // bf16 elems per A-plane row (128 + 8 pad)
#define CS_LD  36

// ---------------- scratch ----------------------------------------------------
__device__ float g_X[(size_t)3 * TSTEPS * BATCH * NH];
__device__ float g_h[2][BATCH * NH];
__device__ float g_z[BATCH * NH];
__device__ float g_rh[BATCH * NH];
__device__ unsigned g_count = 0;
__device__ unsigned g_gen = 0;

// split fp32 -> bf16 hi + bf16 lo (residual)
__device__ __forceinline__ void split1(float v, __nv_bfloat16& h, __nv_bfloat16& l) {
    h = __float2bfloat16(v);
    l = __float2bfloat16(v - __bfloat162float(h));
}
__device__ __forceinline__ void store_split4(float4 v, __nv_bfloat16* ph, __nv_bfloat16* pl) {
    __nv_bfloat16 h0, h1, h2, h3, l0, l1, l2, l3;
    split1(v.x, h0, l0); split1(v.y, h1, l1);
    split1(v.z, h2, l2); split1(v.w, h3, l3);
    ((__nv_bfloat162*)ph)[0] = __nv_bfloat162(h0, h1);
    ((__nv_bfloat162*)ph)[1] = __nv_bfloat162(h2, h3);
    ((__nv_bfloat162*)pl)[0] = __nv_bfloat162(l0, l1);
    ((__nv_bfloat162*)pl)[1] = __nv_bfloat162(l2, l3);
}

// ---------------- grid-wide barrier ------------------------------------------
__device__ __forceinline__ void grid_barrier(unsigned nb) {
    __syncthreads();
    if (threadIdx.x == 0) {
        __threadfence();
        volatile unsigned* genp = &g_gen;
        unsigned gen = *genp;
        unsigned prev = atomicAdd(&g_count, 1u);
        if (prev == nb - 1u) {
            g_count = 0u;
            __threadfence();
            atomicExch((unsigned*)&g_gen, gen + 1u);
        } else {
            while (*genp == gen) { __nanosleep(32); }
        }
        __threadfence();
    }
    __syncthreads();
}

// ---------------- init h -----------------------------------------------------
__global__ void init_h_kernel(const float* __restrict__ h0) {
    int i = blockIdx.x * blockDim.x + threadIdx.x;
    g_h[0][i] = h0[i];
}

// ---------------- phase A: X[g] = input @ Wi_g^T  (bf16 3-term) ---------------
// C tile 64x64, 256 threads, 8 warps each 16x32 (2 n-tiles), KC = 64.
__global__ void __launch_bounds__(256) input_proj_kernel(
    const float* __restrict__ input,
    const float* __restrict__ Wiz, const float* __restrict__ Wir,
    const float* __restrict__ Wih)
{
    __shared__ __nv_bfloat16 Ah[64 * 72], Al[64 * 72];
    __shared__ __nv_bfloat16 Bh[64 * 72], Bl[64 * 72];
    const int tid = threadIdx.x;
    const int tileN = blockIdx.x % 48;
    const int tileM = blockIdx.x / 48;
    const int gate = tileN >> 4;
    const int n0 = (tileN & 15) << 6;
    const int m0 = tileM << 6;
    const float* W = (gate == 0) ? Wiz : ((gate == 1) ? Wir : Wih);
    const float* Abp = input + (size_t)m0 * NIN;
    const float* Bbp = W + (size_t)n0 * NIN;

    const int w = tid >> 5;
    const int r0 = (w >> 1) << 4;   // 0..48
    const int c0 = (w & 1) << 5;    // 0 or 32

    wmma::fragment<wmma::accumulator, 16, 16, 16, float> hh0, hl0, lh0, hh1, hl1, lh1;
    wmma::fill_fragment(hh0, 0.0f); wmma::fill_fragment(hl0, 0.0f); wmma::fill_fragment(lh0, 0.0f);
    wmma::fill_fragment(hh1, 0.0f); wmma::fill_fragment(hl1, 0.0f); wmma::fill_fragment(lh1, 0.0f);

    for (int k0 = 0; k0 < NIN; k0 += 64) {
        __syncthreads();
#pragma unroll
        for (int it = 0; it < 4; it++) {
            int f = tid + (it << 8);          // 1024 float4 per matrix
            int row = f >> 4;
            int c = (f & 15) << 2;
            float4 va = *(const float4*)(Abp + (size_t)row * NIN + k0 + c);
            store_split4(va, Ah + row * 72 + c, Al + row * 72 + c);
            float4 vb = *(const float4*)(Bbp + (size_t)row * NIN + k0 + c);
            store_split4(vb, Bh + row * 72 + c, Bl + row * 72 + c);
        }
        __syncthreads();
#pragma unroll
        for (int k16 = 0; k16 < 64; k16 += 16) {
            wmma::fragment<wmma::matrix_a, 16, 16, 16, __nv_bfloat16, wmma::row_major> ah, al;
            wmma::fragment<wmma::matrix_b, 16, 16, 16, __nv_bfloat16, wmma::col_major> bh0, bl0, bh1, bl1;
            wmma::load_matrix_sync(ah, Ah + r0 * 72 + k16, 72);
            wmma::load_matrix_sync(al, Al + r0 * 72 + k16, 72);
            wmma::load_matrix_sync(bh0, Bh + c0 * 72 + k16, 72);
            wmma::load_matrix_sync(bl0, Bl + c0 * 72 + k16, 72);
            wmma::load_matrix_sync(bh1, Bh + (c0 + 16) * 72 + k16, 72);
            wmma::load_matrix_sync(bl1, Bl + (c0 + 16) * 72 + k16, 72);
            wmma::mma_sync(hh0, ah, bh0, hh0);
            wmma::mma_sync(hl0, ah, bl0, hl0);
            wmma::mma_sync(lh0, al, bh0, lh0);
            wmma::mma_sync(hh1, ah, bh1, hh1);
            wmma::mma_sync(hl1, ah, bl1, hl1);
            wmma::mma_sync(lh1, al, bh1, lh1);
        }
    }
#pragma unroll
    for (int i = 0; i < hh0.num_elements; i++) {
        hh0.x[i] += hl0.x[i] + lh0.x[i];
        hh1.x[i] += hl1.x[i] + lh1.x[i];
    }
    float* outp = g_X + ((size_t)gate * TSTEPS * BATCH + m0) * NH + n0;
    wmma::store_matrix_sync(outp + (size_t)r0 * NH + c0, hh0, NH, wmma::mem_row_major);
    wmma::store_matrix_sync(outp + (size_t)r0 * NH + c0 + 16, hh1, NH, wmma::mem_row_major);
}

// ---------------- phase B per-step tile GEMM: C[64x32] = A[64x1024] @ Ws^T ----
// W bf16 hi/lo planes SMEM-resident; A chunked 128-wide, double-buffered.
__device__ __forceinline__ void tile_gemm(const float* __restrict__ A,
                                          const __nv_bfloat16* __restrict__ Wh,
                                          const __nv_bfloat16* __restrict__ Wl,
                                          __nv_bfloat16* __restrict__ Ahs,
                                          __nv_bfloat16* __restrict__ Als,
                                          float* __restrict__ Cs,
                                          int tid)
{
    const int w = tid >> 5;
    const int r0 = (w >> 1) << 4;   // 0,16,32,48
    const int c0 = (w & 1) << 4;    // 0,16

    wmma::fragment<wmma::accumulator, 16, 16, 16, float> hh, hl, lh;
    wmma::fill_fragment(hh, 0.0f);
    wmma::fill_fragment(hl, 0.0f);
    wmma::fill_fragment(lh, 0.0f);

    float4 v[8];
#pragma unroll
    for (int it = 0; it < 8; it++) {
        int f = tid + (it << 8);
        v[it] = *(const float4*)(A + (size_t)(f >> 5) * NH + ((f & 31) << 2));
    }

    int buf = 0;
    for (int kc = 0; kc < NH; kc += 128) {
        __nv_bfloat16* Ahb = Ahs + buf * (64 * ALD);
        __nv_bfloat16* Alb = Als + buf * (64 * ALD);
#pragma unroll
        for (int it = 0; it < 8; it++) {
            int f = tid + (it << 8);
            int off = (f >> 5) * ALD + ((f & 31) << 2);
            store_split4(v[it], Ahb + off, Alb + off);
        }
        if (kc + 128 < NH) {
#pragma unroll
            for (int it = 0; it < 8; it++) {
                int f = tid + (it << 8);
                v[it] = *(const float4*)(A + (size_t)(f >> 5) * NH + kc + 128 + ((f & 31) << 2));
            }
        }
        __syncthreads();
#pragma unroll
        for (int k16 = 0; k16 < 128; k16 += 16) {
            wmma::fragment<wmma::matrix_a, 16, 16, 16, __nv_bfloat16, wmma::row_major> ah, al;
            wmma::fragment<wmma::matrix_b, 16, 16, 16, __nv_bfloat16, wmma::col_major> bh, bl;
            wmma::load_matrix_sync(ah, Ahb + r0 * ALD + k16, ALD);
            wmma::load_matrix_sync(al, Alb + r0 * ALD + k16, ALD);
            wmma::load_matrix_sync(bh, Wh + c0 * WLD + kc + k16, WLD);
            wmma::load_matrix_sync(bl, Wl + c0 * WLD + kc + k16, WLD);
            wmma::mma_sync(hh, ah, bh, hh);
            wmma::mma_sync(hl, ah, bl, hl);
            wmma::mma_sync(lh, al, bh, lh);
        }
        buf ^= 1;
    }
#pragma unroll
    for (int i = 0; i < hh.num_elements; i++) hh.x[i] += hl.x[i] + lh.x[i];
    wmma::store_matrix_sync(Cs + r0 * CS_LD + c0, hh, CS_LD, wmma::mem_row_major);
    __syncthreads();
}

// ---------------- phase B persistent kernel ----------------------------------
// blocks 0..31: z gate, 32..63: r gate (+ r*h), 64..95: candidate + update.
__global__ void __launch_bounds__(256, 1) gru_step_kernel(
    const float* __restrict__ Whz, const float* __restrict__ Whr,
    const float* __restrict__ Whh,
    const float* __restrict__ Whz_b, const float* __restrict__ Whr_b,
    const float* __restrict__ Whh_b,
    const float* __restrict__ Wiz_b, const float* __restrict__ Wir_b,
    const float* __restrict__ Wih_b,
    const void* __restrict__ lengths,
    float* __restrict__ out, int write_last)
{
    extern __shared__ __nv_bfloat16 sm[];
    __nv_bfloat16* Wh  = sm;                       // [32][WLD]
    __nv_bfloat16* Wl  = Wh + 32 * WLD;            // [32][WLD]
    __nv_bfloat16* Ahs = Wl + 32 * WLD;            // 2 x [64][ALD]
    __nv_bfloat16* Als = Ahs + 2 * 64 * ALD;       // 2 x [64][ALD]
    float* Cs  = (float*)(Als + 2 * 64 * ALD);     // [64][CS_LD]
    float* bia = Cs + 64 * CS_LD;                  // [32]
    int*  slen = (int*)(bia + 32);                 // [64]

    const int tid = threadIdx.x;
    const int b = blockIdx.x;
    int role, n0;
    const float *W, *bh, *bi;
    if (b < 32)      { role = 0; n0 = b * 32;        W = Whz; bh = Whz_b; bi = Wiz_b; }
    else if (b < 64) { role = 1; n0 = (b - 32) * 32; W = Whr; bh = Whr_b; bi = Wir_b; }
    else             { role = 2; n0 = (b - 64) * 32; W = Whh; bh = Whh_b; bi = Wih_b; }

    // preload & split this block's 32x1024 weight slice
    const float* Wb = W + (size_t)n0 * NH;
    for (int f = tid; f < 32 * 256; f += 256) {
        int row = f >> 8;
        int c = (f & 255) << 2;
        float4 v = *(const float4*)(Wb + (size_t)row * NH + c);
        store_split4(v, Wh + row * WLD + c, Wl + row * WLD + c);
    }
    if (tid < 32) bia[tid] = bh[n0 + tid] + bi[n0 + tid];
    // lengths dtype auto-detect: int64 -> word[1]==0 (lengths[0] in 1..512);
    // int32 -> word[1] = lengths[1] >= 1.
    {
        const int* L32 = (const int*)lengths;
        int is64 = (L32[1] == 0);
        if (tid < BATCH)
            slen[tid] = is64 ? (int)((const long long*)lengths)[tid] : L32[tid];
    }
    __syncthreads();

    const size_t xstride = (size_t)BATCH * NH;
    const float* Xg = g_X + (size_t)role * TSTEPS * xstride;

    int cur = 0;
    for (int t = 0; t < TSTEPS; t++) {
        if (role < 2) {
            tile_gemm(g_h[cur], Wh, Wl, Ahs, Als, Cs, tid);
            const float* Xt = Xg + (size_t)t * xstride;
            for (int i = tid; i < 2048; i += 256) {
                int m = i >> 5, n = i & 31;
                float pre = Cs[m * CS_LD + n] + bia[n] + Xt[(size_t)m * NH + n0 + n];
                float s = 1.0f / (1.0f + expf(-pre));
                if (role == 0) g_z[m * NH + n0 + n] = s;
                else           g_rh[m * NH + n0 + n] = s * g_h[cur][m * NH + n0 + n];
            }
        }
        grid_barrier(NBLK_P);
        if (role == 2) {
            tile_gemm(g_rh, Wh, Wl, Ahs, Als, Cs, tid);
            const float* Xt = Xg + (size_t)t * xstride;
            float* hn_buf = g_h[cur ^ 1];
            const float* hp_buf = g_h[cur];
            for (int i = tid; i < 2048; i += 256) {
                int m = i >> 5, n = i & 31;
                int gn = n0 + n;
                float pre = Cs[m * CS_LD + n] + bia[n] + Xt[(size_t)m * NH + gn];
                float hc = tanhf(pre);
                float z = g_z[m * NH + gn];
                float hp = hp_buf[m * NH + gn];
                float hn = (1.0f - z) * hp + z * hc;
                if (t >= slen[m]) hn = hp;
                hn_buf[m * NH + gn] = hn;
                out[(size_t)t * xstride + (size_t)m * NH + gn] = hn;
            }
        }
        grid_barrier(NBLK_P);
        cur ^= 1;
    }
    if (role == 2 && write_last) {
        for (int i = tid; i < 2048; i += 256) {
            int m = i >> 5, n = i & 31;
            out[(size_t)TSTEPS * xstride + (size_t)m * NH + n0 + n] =
                g_h[cur][m * NH + n0 + n];
        }
    }
}

// ---------------- launch ------------------------------------------------------
extern "C" void kernel_launch(void* const* d_in, const int* in_sizes, int n_in,
                              void* d_out, int out_size)
{
    const float* input = (const float*)d_in[0];
    const float* h0    = (const float*)d_in[1];
    const float* Wiz_w = (const float*)d_in[2];
    const float* Wiz_b = (const float*)d_in[3];
    const float* Wir_w = (const float*)d_in[4];
    const float* Wir_b = (const float*)d_in[5];
    const float* Wih_w = (const float*)d_in[6];
    const float* Wih_b = (const float*)d_in[7];
    const float* Whz_w = (const float*)d_in[8];
    const float* Whz_b = (const float*)d_in[9];
    const float* Whr_w = (const float*)d_in[10];
    const float* Whr_b = (const float*)d_in[11];
    const float* Whh_w = (const float*)d_in[12];
    const float* Whh_b = (const float*)d_in[13];
    const void*  lengths = d_in[14];

    init_h_kernel<<<64, 1024>>>(h0);
    input_proj_kernel<<<512 * 48, 256>>>(input, Wiz_w, Wir_w, Wih_w);

    size_t smem_bytes = (size_t)(2 * 32 * WLD + 4 * 64 * ALD) * sizeof(__nv_bfloat16)
                      + (size_t)(64 * CS_LD + 32) * sizeof(float) + 64 * sizeof(int);
    cudaFuncSetAttribute(gru_step_kernel,
                         cudaFuncAttributeMaxDynamicSharedMemorySize, (int)smem_bytes);
    int write_last = (out_size >= TSTEPS * BATCH * NH + BATCH * NH) ? 1 : 0;
    gru_step_kernel<<<NBLK_P, 256, smem_bytes>>>(
        Whz_w, Whr_w, Whh_w, Whz_b, Whr_b, Whh_b,
        Wiz_b, Wir_b, Wih_b, lengths, (float*)d_out, write_last);
}

// round 4
// speedup vs baseline: 2.2089x; 2.2089x over previous
#include <cuda_runtime.h>
#include <cuda_bf16.h>
#include <cstdint>
#include <math.h>

#define TSTEPS 512
#define BATCH  64
#define NIN    512
#define NH     1024
#define NBLK   96

// ============================ global scratch ================================
__device__ float g_X[(size_t)3 * TSTEPS * BATCH * NH];   // input projections
__device__ float g_h32[BATCH * NH];                      // h (fp32, plain)
__device__ float g_z[BATCH * NH];                        // z gate (plain)
// A-operand planes in mma fragment order: frag(kf,mf) -> uint4[frag*32 + lane]
__device__ uint4 g_hhf[8192], g_hlf[8192];               // h split planes
__device__ uint4 g_rhhf[8192], g_rhlf[8192];             // r*h split planes
__device__ unsigned g_count = 0, g_gen = 0;

// ============================ helpers =======================================
__device__ __forceinline__ uint32_t bfpack(float x, float y) {
    __nv_bfloat162 t = __floats2bfloat162_rn(x, y);
    return *(uint32_t*)&t;
}
__device__ __forceinline__ void splitp(float x, float y, uint32_t& hi, uint32_t& lo) {
    float hx = __bfloat162float(__float2bfloat16(x));
    float hy = __bfloat162float(__float2bfloat16(y));
    hi = bfpack(hx, hy);
    lo = bfpack(x - hx, y - hy);
}
__device__ __forceinline__ void mma16816(float* c, const uint32_t* a, const uint32_t* b) {
    asm volatile("mma.sync.aligned.m16n8k16.row.col.f32.bf16.bf16.f32 "
        "{%0,%1,%2,%3},{%4,%5,%6,%7},{%8,%9},{%0,%1,%2,%3};"
        : "+f"(c[0]), "+f"(c[1]), "+f"(c[2]), "+f"(c[3])
        : "r"(a[0]), "r"(a[1]), "r"(a[2]), "r"(a[3]), "r"(b[0]), "r"(b[1]));
}

__device__ __forceinline__ void grid_barrier(unsigned nb) {
    __syncthreads();
    if (threadIdx.x == 0) {
        __threadfence();
        volatile unsigned* genp = &g_gen;
        unsigned gen = *genp;
        unsigned prev = atomicAdd(&g_count, 1u);
        if (prev == nb - 1u) {
            g_count = 0u;
            __threadfence();
            atomicExch((unsigned*)&g_gen, gen + 1u);
        } else {
            while (*genp == gen) { __nanosleep(32); }
        }
        __threadfence();
    }
    __syncthreads();
}

// ======================= phase A: input projections =========================
// block: 128m x 128n tile, K=512 in 4 chunks of 128. 3-term bf16 split.
// smem frag-order staging; warps: 4 m-groups (m32) x 2 n-groups (n64).
#define PA_AH 0
#define PA_AL 32768
#define PA_WH 65536
#define PA_WL 98304
#define PA_SMEM 131072

__global__ void __launch_bounds__(256) input_proj_kernel(
    const float* __restrict__ input,
    const float* __restrict__ Wiz, const float* __restrict__ Wir,
    const float* __restrict__ Wih)
{
    extern __shared__ char sm[];
    uint4* Ah = (uint4*)(sm + PA_AH);
    uint4* Al = (uint4*)(sm + PA_AL);
    uint2* Wh = (uint2*)(sm + PA_WH);
    uint2* Wl = (uint2*)(sm + PA_WL);
    const int tid = threadIdx.x, wid = tid >> 5, lane = tid & 31;
    const int ntile = blockIdx.x % 24, mtile = blockIdx.x / 24;
    const int gate = ntile >> 3, n0g = (ntile & 7) * 128, m0 = mtile * 128;
    const float* W = (gate == 0) ? Wiz : ((gate == 1) ? Wir : Wih);
    const int mg = wid & 3, ng = wid >> 2;

    float c[2][8][4];
#pragma unroll
    for (int i = 0; i < 2; i++)
#pragma unroll
        for (int j = 0; j < 8; j++)
#pragma unroll
            for (int k = 0; k < 4; k++) c[i][j][k] = 0.0f;

    for (int ch = 0; ch < 4; ch++) {
        const int k0 = ch * 128;
        __syncthreads();
        // stage A tile (frag-order, split planes)
#pragma unroll
        for (int it = 0; it < 8; it++) {
            int idx = tid + (it << 8);
            int frag = idx >> 5, l = idx & 31;
            int kf = frag >> 3, mf = frag & 7;
            int r = l >> 2, c2 = (l & 3) * 2;
            const float* src = input + (size_t)(m0 + mf * 16 + r) * NIN + k0 + kf * 16 + c2;
            float2 p0 = *(const float2*)(src);
            float2 p1 = *(const float2*)(src + 8 * NIN);
            float2 p2 = *(const float2*)(src + 8);
            float2 p3 = *(const float2*)(src + 8 * NIN + 8);
            uint32_t h0, h1, h2, h3, lo0, lo1, lo2, lo3;
            splitp(p0.x, p0.y, h0, lo0); splitp(p1.x, p1.y, h1, lo1);
            splitp(p2.x, p2.y, h2, lo2); splitp(p3.x, p3.y, h3, lo3);
            Ah[frag * 32 + l] = make_uint4(h0, h1, h2, h3);
            Al[frag * 32 + l] = make_uint4(lo0, lo1, lo2, lo3);
        }
        // stage W tile (B-frag order, split planes)
#pragma unroll
        for (int it = 0; it < 16; it++) {
            int idx = tid + (it << 8);
            int frag = idx >> 5, l = idx & 31;
            int kf = frag >> 4, nf = frag & 15;
            int n = nf * 8 + (l >> 2), k = kf * 16 + (l & 3) * 2;
            const float* src = W + (size_t)(n0g + n) * NIN + k0 + k;
            float2 q0 = *(const float2*)src;
            float2 q1 = *(const float2*)(src + 8);
            uint32_t h0, h1, lo0, lo1;
            splitp(q0.x, q0.y, h0, lo0); splitp(q1.x, q1.y, h1, lo1);
            Wh[frag * 32 + l] = make_uint2(h0, h1);
            Wl[frag * 32 + l] = make_uint2(lo0, lo1);
        }
        __syncthreads();
#pragma unroll 2
        for (int s = 0; s < 8; s++) {
            uint4 ah[2], al[2];
            uint2 bh[8], bl[8];
            ah[0] = Ah[(s * 8 + mg * 2 + 0) * 32 + lane];
            ah[1] = Ah[(s * 8 + mg * 2 + 1) * 32 + lane];
            al[0] = Al[(s * 8 + mg * 2 + 0) * 32 + lane];
            al[1] = Al[(s * 8 + mg * 2 + 1) * 32 + lane];
#pragma unroll
            for (int nf = 0; nf < 8; nf++) {
                bh[nf] = Wh[(s * 16 + ng * 8 + nf) * 32 + lane];
                bl[nf] = Wl[(s * 16 + ng * 8 + nf) * 32 + lane];
            }
#pragma unroll
            for (int mf = 0; mf < 2; mf++)
#pragma unroll
                for (int nf = 0; nf < 8; nf++) {
                    mma16816(c[mf][nf], &ah[mf].x, &bh[nf].x);
                    mma16816(c[mf][nf], &al[mf].x, &bh[nf].x);
                    mma16816(c[mf][nf], &ah[mf].x, &bl[nf].x);
                }
        }
    }
    // epilogue: direct frag->global stores
    const int r = lane >> 2, c2 = (lane & 3) * 2;
#pragma unroll
    for (int mf = 0; mf < 2; mf++)
#pragma unroll
        for (int nf = 0; nf < 8; nf++) {
            size_t row = (size_t)(m0 + (mg * 2 + mf) * 16 + r);
            size_t base = ((size_t)gate * TSTEPS * BATCH + row) * NH
                        + n0g + (ng * 8 + nf) * 8 + c2;
            *(float2*)(g_X + base) = make_float2(c[mf][nf][0], c[mf][nf][1]);
            *(float2*)(g_X + base + (size_t)8 * NH) = make_float2(c[mf][nf][2], c[mf][nf][3]);
        }
}

// ======================= phase B: persistent GRU ============================
#define PBW_H   0                       // W hi plane (B-frag order) 64KB
#define PBW_L   65536                   // W lo plane 64KB
#define PB_SCR  131072                  // float[4][64][36] partials
#define PB_SBUF 167936                  // float[64][36] stage values
#define PB_BIA  177152                  // float[32]
#define PB_SLEN 177280                  // int[64]
#define PB_SMEM 177664

// C[64x32] = A[64x1024] @ Wslice^T, 3-term. warps: 2 m-groups x 4 k-groups.
__device__ __forceinline__ void gemm_stage(const uint4* __restrict__ Aph,
                                           const uint4* __restrict__ Apl,
                                           const uint2* __restrict__ Wh,
                                           const uint2* __restrict__ Wl,
                                           float* __restrict__ scr,
                                           int wid, int lane)
{
    const int mg = wid & 1, kg = wid >> 1;
    float c[2][4][4];
#pragma unroll
    for (int i = 0; i < 2; i++)
#pragma unroll
        for (int j = 0; j < 4; j++)
#pragma unroll
            for (int k = 0; k < 4; k++) c[i][j][k] = 0.0f;

#pragma unroll 2
    for (int s = 0; s < 16; s++) {
        const int kf = kg * 16 + s;
        uint4 ah[2], al[2];
        uint2 bh[4], bl[4];
        ah[0] = Aph[(kf * 4 + mg * 2 + 0) * 32 + lane];
        ah[1] = Aph[(kf * 4 + mg * 2 + 1) * 32 + lane];
        al[0] = Apl[(kf * 4 + mg * 2 + 0) * 32 + lane];
        al[1] = Apl[(kf * 4 + mg * 2 + 1) * 32 + lane];
#pragma unroll
        for (int nf = 0; nf < 4; nf++) {
            bh[nf] = Wh[(kf * 4 + nf) * 32 + lane];
            bl[nf] = Wl[(kf * 4 + nf) * 32 + lane];
        }
#pragma unroll
        for (int mf = 0; mf < 2; mf++)
#pragma unroll
            for (int nf = 0; nf < 4; nf++) {
                mma16816(c[mf][nf], &ah[mf].x, &bh[nf].x);
                mma16816(c[mf][nf], &al[mf].x, &bh[nf].x);
                mma16816(c[mf][nf], &ah[mf].x, &bl[nf].x);
            }
    }
    const int r = lane >> 2, c2 = (lane & 3) * 2;
#pragma unroll
    for (int mf = 0; mf < 2; mf++)
#pragma unroll
        for (int nf = 0; nf < 4; nf++) {
            float* p = scr + ((kg * 64 + mg * 32 + mf * 16 + r) * 36 + nf * 8 + c2);
            *(float2*)p = make_float2(c[mf][nf][0], c[mf][nf][1]);
            *(float2*)(p + 8 * 36) = make_float2(c[mf][nf][2], c[mf][nf][3]);
        }
}

// pack sbuf[64][36] (fp32, values for this block's 32 k-cols) into A-frag planes
__device__ __forceinline__ void pack_planes(const float* __restrict__ sbuf,
                                            uint4* __restrict__ dsth,
                                            uint4* __restrict__ dstl,
                                            int kfbase, int tid)
{
    const int f = tid >> 5, l = tid & 31;
    const int mf = f & 3, kfo = f >> 2;
    const int r = l >> 2, c2 = (l & 3) * 2;
    const float* p = sbuf + (mf * 16 + r) * 36 + kfo * 16 + c2;
    uint32_t h0, h1, h2, h3, lo0, lo1, lo2, lo3;
    splitp(p[0], p[1], h0, lo0);
    splitp(p[8 * 36], p[8 * 36 + 1], h1, lo1);
    splitp(p[8], p[9], h2, lo2);
    splitp(p[8 * 36 + 8], p[8 * 36 + 9], h3, lo3);
    const int frag = (kfbase + kfo) * 4 + mf;
    dsth[frag * 32 + l] = make_uint4(h0, h1, h2, h3);
    dstl[frag * 32 + l] = make_uint4(lo0, lo1, lo2, lo3);
}

__global__ void __launch_bounds__(256, 1) gru_step_kernel(
    const float* __restrict__ h0in,
    const float* __restrict__ Whz, const float* __restrict__ Whr,
    const float* __restrict__ Whh,
    const float* __restrict__ Whz_b, const float* __restrict__ Whr_b,
    const float* __restrict__ Whh_b,
    const float* __restrict__ Wiz_b, const float* __restrict__ Wir_b,
    const float* __restrict__ Wih_b,
    const void* __restrict__ lengths,
    float* __restrict__ out, int write_last)
{
    extern __shared__ char sm[];
    uint2* Wh = (uint2*)(sm + PBW_H);
    uint2* Wl = (uint2*)(sm + PBW_L);
    float* scr = (float*)(sm + PB_SCR);
    float* sbuf = (float*)(sm + PB_SBUF);
    float* bia = (float*)(sm + PB_BIA);
    int* slen = (int*)(sm + PB_SLEN);

    const int tid = threadIdx.x, wid = tid >> 5, lane = tid & 31;
    const int b = blockIdx.x;
    int role, gn0;
    const float *W, *bh, *bi;
    if (b < 32)      { role = 0; gn0 = b * 32;        W = Whz; bh = Whz_b; bi = Wiz_b; }
    else if (b < 64) { role = 1; gn0 = (b - 32) * 32; W = Whr; bh = Whr_b; bi = Wir_b; }
    else             { role = 2; gn0 = (b - 64) * 32; W = Whh; bh = Whh_b; bi = Wih_b; }

    // pack W slice (32 n-cols x 1024 K) into B-frag-order split planes
#pragma unroll 4
    for (int it = 0; it < 32; it++) {
        int idx = tid + (it << 8);
        int frag = idx >> 5, l = idx & 31;
        int kf = frag >> 2, nf = frag & 3;
        int n = nf * 8 + (l >> 2), k = kf * 16 + (l & 3) * 2;
        const float* src = W + (size_t)(gn0 + n) * NH + k;
        float2 q0 = *(const float2*)src;
        float2 q1 = *(const float2*)(src + 8);
        uint32_t h0, h1, lo0, lo1;
        splitp(q0.x, q0.y, h0, lo0); splitp(q1.x, q1.y, h1, lo1);
        Wh[frag * 32 + l] = make_uint2(h0, h1);
        Wl[frag * 32 + l] = make_uint2(lo0, lo1);
    }
    if (tid < 32) bia[tid] = bh[gn0 + tid] + bi[gn0 + tid];
    {   // lengths dtype auto-detect (int64 -> high word of elem0 is 0)
        const int* L32 = (const int*)lengths;
        int is64 = (L32[1] == 0);
        if (tid < BATCH)
            slen[tid] = is64 ? (int)((const long long*)lengths)[tid] : L32[tid];
    }
    // init h: plain fp32 + frag-order split planes (role-2 blocks cover all cols)
    if (role == 2) {
        int m = tid >> 2, nq = (tid & 3) * 8;
        const float* src = h0in + (size_t)m * NH + gn0 + nq;
        float4 v0 = *(const float4*)src;
        float4 v1 = *(const float4*)(src + 4);
        *(float4*)(g_h32 + (size_t)m * NH + gn0 + nq) = v0;
        *(float4*)(g_h32 + (size_t)m * NH + gn0 + nq + 4) = v1;
        // pack directly from h0 global
        const int f = tid >> 5, l = tid & 31;
        const int mf = f & 3, kfo = f >> 2;
        const int r = l >> 2, c2 = (l & 3) * 2;
        const float* p = h0in + (size_t)(mf * 16 + r) * NH + gn0 + kfo * 16 + c2;
        uint32_t h0, h1, h2, h3, lo0, lo1, lo2, lo3;
        splitp(p[0], p[1], h0, lo0);
        splitp(p[8 * NH], p[8 * NH + 1], h1, lo1);
        splitp(p[8], p[9], h2, lo2);
        splitp(p[8 * NH + 8], p[8 * NH + 9], h3, lo3);
        const int frag = ((b - 64) * 2 + kfo) * 4 + mf;
        g_hhf[frag * 32 + l] = make_uint4(h0, h1, h2, h3);
        g_hlf[frag * 32 + l] = make_uint4(lo0, lo1, lo2, lo3);
    }
    __syncthreads();
    grid_barrier(NBLK);

    const int m = tid >> 2, nq = (tid & 3) * 8;

    for (int t = 0; t < TSTEPS; t++) {
        if (role < 2) {
            gemm_stage(g_hhf, g_hlf, Wh, Wl, scr, wid, lane);
            __syncthreads();
            // reduce 4 k-partials + bias + X
            float pre[8];
            {
                const float* Xt = g_X + ((size_t)role * TSTEPS * BATCH + (size_t)t * BATCH + m) * NH + gn0 + nq;
                float4 x0 = *(const float4*)Xt;
                float4 x1 = *(const float4*)(Xt + 4);
                pre[0] = x0.x; pre[1] = x0.y; pre[2] = x0.z; pre[3] = x0.w;
                pre[4] = x1.x; pre[5] = x1.y; pre[6] = x1.z; pre[7] = x1.w;
#pragma unroll
                for (int kg = 0; kg < 4; kg++) {
                    const float* p = scr + ((kg * 64 + m) * 36 + nq);
                    float4 a = *(const float4*)p;
                    float4 bb = *(const float4*)(p + 4);
                    pre[0] += a.x; pre[1] += a.y; pre[2] += a.z; pre[3] += a.w;
                    pre[4] += bb.x; pre[5] += bb.y; pre[6] += bb.z; pre[7] += bb.w;
                }
#pragma unroll
                for (int j = 0; j < 8; j++) pre[j] += bia[nq + j];
            }
            if (role == 0) {
                float zv[8];
#pragma unroll
                for (int j = 0; j < 8; j++) zv[j] = 1.0f / (1.0f + expf(-pre[j]));
                float* dst = g_z + (size_t)m * NH + gn0 + nq;
                *(float4*)dst = make_float4(zv[0], zv[1], zv[2], zv[3]);
                *(float4*)(dst + 4) = make_float4(zv[4], zv[5], zv[6], zv[7]);
            } else {
                const float* hp = g_h32 + (size_t)m * NH + gn0 + nq;
#pragma unroll
                for (int j = 0; j < 8; j++) {
                    float s = 1.0f / (1.0f + expf(-pre[j]));
                    sbuf[m * 36 + nq + j] = s * hp[j];
                }
                __syncthreads();
                pack_planes(sbuf, g_rhhf, g_rhlf, (b - 32) * 2, tid);
            }
        }
        grid_barrier(NBLK);
        if (role == 2) {
            gemm_stage(g_rhhf, g_rhlf, Wh, Wl, scr, wid, lane);
            __syncthreads();
            float pre[8];
            {
                const float* Xt = g_X + ((size_t)2 * TSTEPS * BATCH + (size_t)t * BATCH + m) * NH + gn0 + nq;
                float4 x0 = *(const float4*)Xt;
                float4 x1 = *(const float4*)(Xt + 4);
                pre[0] = x0.x; pre[1] = x0.y; pre[2] = x0.z; pre[3] = x0.w;
                pre[4] = x1.x; pre[5] = x1.y; pre[6] = x1.z; pre[7] = x1.w;
#pragma unroll
                for (int kg = 0; kg < 4; kg++) {
                    const float* p = scr + ((kg * 64 + m) * 36 + nq);
                    float4 a = *(const float4*)p;
                    float4 bb = *(const float4*)(p + 4);
                    pre[0] += a.x; pre[1] += a.y; pre[2] += a.z; pre[3] += a.w;
                    pre[4] += bb.x; pre[5] += bb.y; pre[6] += bb.z; pre[7] += bb.w;
                }
#pragma unroll
                for (int j = 0; j < 8; j++) pre[j] += bia[nq + j];
            }
            const float* zp = g_z + (size_t)m * NH + gn0 + nq;
            float* hp = g_h32 + (size_t)m * NH + gn0 + nq;
            const int sl = slen[m];
            float hn[8];
#pragma unroll
            for (int j = 0; j < 8; j++) {
                float hc = tanhf(pre[j]);
                float z = zp[j];
                float h_ = hp[j];
                float v = (1.0f - z) * h_ + z * hc;
                if (t >= sl) v = h_;
                hn[j] = v;
                sbuf[m * 36 + nq + j] = v;
            }
            *(float4*)hp = make_float4(hn[0], hn[1], hn[2], hn[3]);
            *(float4*)(hp + 4) = make_float4(hn[4], hn[5], hn[6], hn[7]);
            float* op = out + (size_t)t * BATCH * NH + (size_t)m * NH + gn0 + nq;
            *(float4*)op = make_float4(hn[0], hn[1], hn[2], hn[3]);
            *(float4*)(op + 4) = make_float4(hn[4], hn[5], hn[6], hn[7]);
            __syncthreads();
            pack_planes(sbuf, g_hhf, g_hlf, (b - 64) * 2, tid);
        }
        grid_barrier(NBLK);
    }
    if (role == 2 && write_last) {
        const float* hp = g_h32 + (size_t)m * NH + gn0 + nq;
        float* op = out + (size_t)TSTEPS * BATCH * NH + (size_t)m * NH + gn0 + nq;
        *(float4*)op = make_float4(hp[0], hp[1], hp[2], hp[3]);
        *(float4*)(op + 4) = make_float4(hp[4], hp[5], hp[6], hp[7]);
    }
}

// ============================= launch =======================================
extern "C" void kernel_launch(void* const* d_in, const int* in_sizes, int n_in,
                              void* d_out, int out_size)
{
    const float* input = (const float*)d_in[0];
    const float* h0    = (const float*)d_in[1];
    const float* Wiz_w = (const float*)d_in[2];
    const float* Wiz_b = (const float*)d_in[3];
    const float* Wir_w = (const float*)d_in[4];
    const float* Wir_b = (const float*)d_in[5];
    const float* Wih_w = (const float*)d_in[6];
    const float* Wih_b = (const float*)d_in[7];
    const float* Whz_w = (const float*)d_in[8];
    const float* Whz_b = (const float*)d_in[9];
    const float* Whr_w = (const float*)d_in[10];
    const float* Whr_b = (const float*)d_in[11];
    const float* Whh_w = (const float*)d_in[12];
    const float* Whh_b = (const float*)d_in[13];
    const void*  lengths = d_in[14];

    cudaFuncSetAttribute(input_proj_kernel,
                         cudaFuncAttributeMaxDynamicSharedMemorySize, PA_SMEM);
    cudaFuncSetAttribute(gru_step_kernel,
                         cudaFuncAttributeMaxDynamicSharedMemorySize, PB_SMEM);

    input_proj_kernel<<<256 * 24, 256, PA_SMEM>>>(input, Wiz_w, Wir_w, Wih_w);

    int write_last = (out_size >= TSTEPS * BATCH * NH + BATCH * NH) ? 1 : 0;
    gru_step_kernel<<<NBLK, 256, PB_SMEM>>>(
        h0, Whz_w, Whr_w, Whh_w, Whz_b, Whr_b, Whh_b,
        Wiz_b, Wir_b, Wih_b, lengths, (float*)d_out, write_last);
}

// round 5
// speedup vs baseline: 2.2595x; 1.0229x over previous
#include <cuda_runtime.h>
#include <cuda_bf16.h>
#include <cstdint>
#include <math.h>

#define TSTEPS 512
#define BATCH  64
#define NIN    512
#define NH     1024
#define NBLK   96

// ============================ global scratch ================================
__device__ float g_X[(size_t)3 * TSTEPS * BATCH * NH];   // input projections
__device__ float g_h32[BATCH * NH];                      // h (fp32, plain)
__device__ float g_z[BATCH * NH];                        // z gate (plain)
// A-operand planes in mma fragment order: frag(kf,mf) -> uint4[frag*32 + lane]
__device__ uint4 g_hhf[2][8192], g_hlf[2][8192];         // h split planes (parity)
__device__ uint4 g_rhhf[8192], g_rhlf[8192];             // r*h split planes
// producer-consumer flags (monotonic step counters, reset each launch)
__device__ int g_fh[32], g_fr[32], g_fz[32];

// ============================ helpers =======================================
__device__ __forceinline__ uint32_t bfpack(float x, float y) {
    __nv_bfloat162 t = __floats2bfloat162_rn(x, y);
    return *(uint32_t*)&t;
}
__device__ __forceinline__ void splitp(float x, float y, uint32_t& hi, uint32_t& lo) {
    float hx = __bfloat162float(__float2bfloat16(x));
    float hy = __bfloat162float(__float2bfloat16(y));
    hi = bfpack(hx, hy);
    lo = bfpack(x - hx, y - hy);
}
__device__ __forceinline__ void mma16816(float* c, const uint32_t* a, const uint32_t* b) {
    asm volatile("mma.sync.aligned.m16n8k16.row.col.f32.bf16.bf16.f32 "
        "{%0,%1,%2,%3},{%4,%5,%6,%7},{%8,%9},{%0,%1,%2,%3};"
        : "+f"(c[0]), "+f"(c[1]), "+f"(c[2]), "+f"(c[3])
        : "r"(a[0]), "r"(a[1]), "r"(a[2]), "r"(a[3]), "r"(b[0]), "r"(b[1]));
}
__device__ __forceinline__ int ld_acq(const int* p) {
    int v;
    asm volatile("ld.acquire.gpu.global.s32 %0, [%1];" : "=r"(v) : "l"(p) : "memory");
    return v;
}
__device__ __forceinline__ void st_rel(int* p, int v) {
    asm volatile("st.release.gpu.global.s32 [%0], %1;" :: "l"(p), "r"(v) : "memory");
}
// warp waits until flags[base + lane&7] >= target for all 8 producers
__device__ __forceinline__ void warp_wait8(const int* flags, int target) {
    const int i = threadIdx.x & 7;
    if (__all_sync(0xFFFFFFFFu, ld_acq(flags + i) >= target)) return;
    while (!__all_sync(0xFFFFFFFFu, ld_acq(flags + i) >= target)) __nanosleep(20);
}

// =================== init: reset flags each launch ==========================
__global__ void init_misc_kernel() {
    int i = threadIdx.x;
    if (i < 32) { g_fh[i] = -1; g_fr[i] = -1; g_fz[i] = -1; }
}

// ======================= phase A: input projections =========================
#define PA_AH 0
#define PA_AL 32768
#define PA_WH 65536
#define PA_WL 98304
#define PA_SMEM 131072

__global__ void __launch_bounds__(256) input_proj_kernel(
    const float* __restrict__ input,
    const float* __restrict__ Wiz, const float* __restrict__ Wir,
    const float* __restrict__ Wih)
{
    extern __shared__ char sm[];
    uint4* Ah = (uint4*)(sm + PA_AH);
    uint4* Al = (uint4*)(sm + PA_AL);
    uint2* Wh = (uint2*)(sm + PA_WH);
    uint2* Wl = (uint2*)(sm + PA_WL);
    const int tid = threadIdx.x, wid = tid >> 5, lane = tid & 31;
    const int ntile = blockIdx.x % 24, mtile = blockIdx.x / 24;
    const int gate = ntile >> 3, n0g = (ntile & 7) * 128, m0 = mtile * 128;
    const float* W = (gate == 0) ? Wiz : ((gate == 1) ? Wir : Wih);
    const int mg = wid & 3, ng = wid >> 2;

    float c[2][8][4];
#pragma unroll
    for (int i = 0; i < 2; i++)
#pragma unroll
        for (int j = 0; j < 8; j++)
#pragma unroll
            for (int k = 0; k < 4; k++) c[i][j][k] = 0.0f;

    for (int ch = 0; ch < 4; ch++) {
        const int k0 = ch * 128;
        __syncthreads();
#pragma unroll
        for (int it = 0; it < 8; it++) {
            int idx = tid + (it << 8);
            int frag = idx >> 5, l = idx & 31;
            int kf = frag >> 3, mf = frag & 7;
            int r = l >> 2, c2 = (l & 3) * 2;
            const float* src = input + (size_t)(m0 + mf * 16 + r) * NIN + k0 + kf * 16 + c2;
            float2 p0 = *(const float2*)(src);
            float2 p1 = *(const float2*)(src + 8 * NIN);
            float2 p2 = *(const float2*)(src + 8);
            float2 p3 = *(const float2*)(src + 8 * NIN + 8);
            uint32_t h0, h1, h2, h3, lo0, lo1, lo2, lo3;
            splitp(p0.x, p0.y, h0, lo0); splitp(p1.x, p1.y, h1, lo1);
            splitp(p2.x, p2.y, h2, lo2); splitp(p3.x, p3.y, h3, lo3);
            Ah[frag * 32 + l] = make_uint4(h0, h1, h2, h3);
            Al[frag * 32 + l] = make_uint4(lo0, lo1, lo2, lo3);
        }
#pragma unroll
        for (int it = 0; it < 16; it++) {
            int idx = tid + (it << 8);
            int frag = idx >> 5, l = idx & 31;
            int kf = frag >> 4, nf = frag & 15;
            int n = nf * 8 + (l >> 2), k = kf * 16 + (l & 3) * 2;
            const float* src = W + (size_t)(n0g + n) * NIN + k0 + k;
            float2 q0 = *(const float2*)src;
            float2 q1 = *(const float2*)(src + 8);
            uint32_t h0, h1, lo0, lo1;
            splitp(q0.x, q0.y, h0, lo0); splitp(q1.x, q1.y, h1, lo1);
            Wh[frag * 32 + l] = make_uint2(h0, h1);
            Wl[frag * 32 + l] = make_uint2(lo0, lo1);
        }
        __syncthreads();
#pragma unroll 2
        for (int s = 0; s < 8; s++) {
            uint4 ah[2], al[2];
            uint2 bh[8], bl[8];
            ah[0] = Ah[(s * 8 + mg * 2 + 0) * 32 + lane];
            ah[1] = Ah[(s * 8 + mg * 2 + 1) * 32 + lane];
            al[0] = Al[(s * 8 + mg * 2 + 0) * 32 + lane];
            al[1] = Al[(s * 8 + mg * 2 + 1) * 32 + lane];
#pragma unroll
            for (int nf = 0; nf < 8; nf++) {
                bh[nf] = Wh[(s * 16 + ng * 8 + nf) * 32 + lane];
                bl[nf] = Wl[(s * 16 + ng * 8 + nf) * 32 + lane];
            }
#pragma unroll
            for (int mf = 0; mf < 2; mf++)
#pragma unroll
                for (int nf = 0; nf < 8; nf++) {
                    mma16816(c[mf][nf], &ah[mf].x, &bh[nf].x);
                    mma16816(c[mf][nf], &al[mf].x, &bh[nf].x);
                    mma16816(c[mf][nf], &ah[mf].x, &bl[nf].x);
                }
        }
    }
    const int r = lane >> 2, c2 = (lane & 3) * 2;
#pragma unroll
    for (int mf = 0; mf < 2; mf++)
#pragma unroll
        for (int nf = 0; nf < 8; nf++) {
            size_t row = (size_t)(m0 + (mg * 2 + mf) * 16 + r);
            size_t base = ((size_t)gate * TSTEPS * BATCH + row) * NH
                        + n0g + (ng * 8 + nf) * 8 + c2;
            *(float2*)(g_X + base) = make_float2(c[mf][nf][0], c[mf][nf][1]);
            *(float2*)(g_X + base + (size_t)8 * NH) = make_float2(c[mf][nf][2], c[mf][nf][3]);
        }
}

// ======================= phase B: persistent GRU ============================
#define PBW_H   0
#define PBW_L   65536
#define PB_SCR  131072                  // float[4][64][36] partials
#define PB_SBUF 167936                  // float[64][36]
#define PB_BIA  177152                  // float[32]
#define PB_SLEN 177280                  // int[64]
#define PB_SMEM 177664

// C[64x32] = A[64x1024] @ Wslice^T, 3-term, depth-2 operand pipeline.
__device__ __forceinline__ void gemm_stage(const uint4* __restrict__ Aph,
                                           const uint4* __restrict__ Apl,
                                           const uint2* __restrict__ Wh,
                                           const uint2* __restrict__ Wl,
                                           float* __restrict__ scr,
                                           int wid, int lane)
{
    const int mg = wid & 1, kg = wid >> 1;
    const int kf0 = kg * 16;
    float c[2][4][4];
#pragma unroll
    for (int i = 0; i < 2; i++)
#pragma unroll
        for (int j = 0; j < 4; j++)
#pragma unroll
            for (int k = 0; k < 4; k++) c[i][j][k] = 0.0f;

    uint4 ah[2][2], al[2][2];
    uint2 bh[2][4], bl[2][4];
    {
        int base = (kf0 * 4 + mg * 2) * 32 + lane;
        ah[0][0] = Aph[base]; ah[0][1] = Aph[base + 32];
        al[0][0] = Apl[base]; al[0][1] = Apl[base + 32];
        int wb = (kf0 * 4) * 32 + lane;
#pragma unroll
        for (int nf = 0; nf < 4; nf++) { bh[0][nf] = Wh[wb + nf * 32]; bl[0][nf] = Wl[wb + nf * 32]; }
    }
#pragma unroll
    for (int s = 0; s < 16; s++) {
        const int cur = s & 1, nxt = cur ^ 1;
        if (s < 15) {
            int kf = kf0 + s + 1;
            int base = (kf * 4 + mg * 2) * 32 + lane;
            ah[nxt][0] = Aph[base]; ah[nxt][1] = Aph[base + 32];
            al[nxt][0] = Apl[base]; al[nxt][1] = Apl[base + 32];
            int wb = (kf * 4) * 32 + lane;
#pragma unroll
            for (int nf = 0; nf < 4; nf++) { bh[nxt][nf] = Wh[wb + nf * 32]; bl[nxt][nf] = Wl[wb + nf * 32]; }
        }
#pragma unroll
        for (int mf = 0; mf < 2; mf++)
#pragma unroll
            for (int nf = 0; nf < 4; nf++) {
                mma16816(c[mf][nf], &ah[cur][mf].x, &bh[cur][nf].x);
                mma16816(c[mf][nf], &al[cur][mf].x, &bh[cur][nf].x);
                mma16816(c[mf][nf], &ah[cur][mf].x, &bl[cur][nf].x);
            }
    }
    const int r = lane >> 2, c2 = (lane & 3) * 2;
#pragma unroll
    for (int mf = 0; mf < 2; mf++)
#pragma unroll
        for (int nf = 0; nf < 4; nf++) {
            float* p = scr + ((kg * 64 + mg * 32 + mf * 16 + r) * 36 + nf * 8 + c2);
            *(float2*)p = make_float2(c[mf][nf][0], c[mf][nf][1]);
            *(float2*)(p + 8 * 36) = make_float2(c[mf][nf][2], c[mf][nf][3]);
        }
}

// pack sbuf[64][36] (fp32 values for this block's 32 cols) into A-frag planes
__device__ __forceinline__ void pack_planes(const float* __restrict__ sbuf,
                                            uint4* __restrict__ dsth,
                                            uint4* __restrict__ dstl,
                                            int kfbase, int tid)
{
    const int f = tid >> 5, l = tid & 31;
    const int mf = f & 3, kfo = f >> 2;
    const int r = l >> 2, c2 = (l & 3) * 2;
    const float* p = sbuf + (mf * 16 + r) * 36 + kfo * 16 + c2;
    uint32_t h0, h1, h2, h3, lo0, lo1, lo2, lo3;
    splitp(p[0], p[1], h0, lo0);
    splitp(p[8 * 36], p[8 * 36 + 1], h1, lo1);
    splitp(p[8], p[9], h2, lo2);
    splitp(p[8 * 36 + 8], p[8 * 36 + 9], h3, lo3);
    const int frag = (kfbase + kfo) * 4 + mf;
    dsth[frag * 32 + l] = make_uint4(h0, h1, h2, h3);
    dstl[frag * 32 + l] = make_uint4(lo0, lo1, lo2, lo3);
}

// reduce 4 K-partials + X + bias into pre[8]
__device__ __forceinline__ void reduce_pre(const float* __restrict__ scr,
                                           const float* __restrict__ bia,
                                           const float4 x0, const float4 x1,
                                           int m, int nq, float* pre)
{
    pre[0] = x0.x; pre[1] = x0.y; pre[2] = x0.z; pre[3] = x0.w;
    pre[4] = x1.x; pre[5] = x1.y; pre[6] = x1.z; pre[7] = x1.w;
#pragma unroll
    for (int kg = 0; kg < 4; kg++) {
        const float* p = scr + ((kg * 64 + m) * 36 + nq);
        float4 a = *(const float4*)p;
        float4 bb = *(const float4*)(p + 4);
        pre[0] += a.x; pre[1] += a.y; pre[2] += a.z; pre[3] += a.w;
        pre[4] += bb.x; pre[5] += bb.y; pre[6] += bb.z; pre[7] += bb.w;
    }
#pragma unroll
    for (int j = 0; j < 8; j++) pre[j] += bia[nq + j];
}

__global__ void __launch_bounds__(256, 1) gru_step_kernel(
    const float* __restrict__ h0in,
    const float* __restrict__ Whz, const float* __restrict__ Whr,
    const float* __restrict__ Whh,
    const float* __restrict__ Whz_b, const float* __restrict__ Whr_b,
    const float* __restrict__ Whh_b,
    const float* __restrict__ Wiz_b, const float* __restrict__ Wir_b,
    const float* __restrict__ Wih_b,
    const void* __restrict__ lengths,
    float* __restrict__ out, int write_last)
{
    extern __shared__ char sm[];
    uint2* Wh = (uint2*)(sm + PBW_H);
    uint2* Wl = (uint2*)(sm + PBW_L);
    float* scr = (float*)(sm + PB_SCR);
    float* sbuf = (float*)(sm + PB_SBUF);
    float* bia = (float*)(sm + PB_BIA);
    int* slen = (int*)(sm + PB_SLEN);

    const int tid = threadIdx.x, wid = tid >> 5, lane = tid & 31;
    const int b = blockIdx.x;
    int role, j;
    const float *W, *bh, *bi;
    if (b < 32)      { role = 0; j = b;      W = Whz; bh = Whz_b; bi = Wiz_b; }
    else if (b < 64) { role = 1; j = b - 32; W = Whr; bh = Whr_b; bi = Wir_b; }
    else             { role = 2; j = b - 64; W = Whh; bh = Whh_b; bi = Wih_b; }
    const int gn0 = j * 32;

    // pack W slice into B-frag-order split planes
#pragma unroll 4
    for (int it = 0; it < 32; it++) {
        int idx = tid + (it << 8);
        int frag = idx >> 5, l = idx & 31;
        int kf = frag >> 2, nf = frag & 3;
        int n = nf * 8 + (l >> 2), k = kf * 16 + (l & 3) * 2;
        const float* src = W + (size_t)(gn0 + n) * NH + k;
        float2 q0 = *(const float2*)src;
        float2 q1 = *(const float2*)(src + 8);
        uint32_t h0, h1, lo0, lo1;
        splitp(q0.x, q0.y, h0, lo0); splitp(q1.x, q1.y, h1, lo1);
        Wh[frag * 32 + l] = make_uint2(h0, h1);
        Wl[frag * 32 + l] = make_uint2(lo0, lo1);
    }
    if (tid < 32) bia[tid] = bh[gn0 + tid] + bi[gn0 + tid];
    {   // lengths dtype auto-detect (int64 -> high word of elem0 is 0)
        const int* L32 = (const int*)lengths;
        int is64 = (L32[1] == 0);
        if (tid < BATCH)
            slen[tid] = is64 ? (int)((const long long*)lengths)[tid] : L32[tid];
    }

    const int m = tid >> 2, nq = (tid & 3) * 8;
    const int kg = wid >> 1;
    float hreg[8];

    if (role == 2) {
        // init h: registers + plain fp32 + frag-order planes parity 0
        const float* src = h0in + (size_t)m * NH + gn0 + nq;
        float4 v0 = *(const float4*)src;
        float4 v1 = *(const float4*)(src + 4);
        hreg[0] = v0.x; hreg[1] = v0.y; hreg[2] = v0.z; hreg[3] = v0.w;
        hreg[4] = v1.x; hreg[5] = v1.y; hreg[6] = v1.z; hreg[7] = v1.w;
        *(float4*)(g_h32 + (size_t)m * NH + gn0 + nq) = v0;
        *(float4*)(g_h32 + (size_t)m * NH + gn0 + nq + 4) = v1;
        {
            const int f = tid >> 5, l = tid & 31;
            const int mf = f & 3, kfo = f >> 2;
            const int r = l >> 2, c2 = (l & 3) * 2;
            const float* p = h0in + (size_t)(mf * 16 + r) * NH + gn0 + kfo * 16 + c2;
            uint32_t h0, h1, h2, h3, lo0, lo1, lo2, lo3;
            splitp(p[0], p[1], h0, lo0);
            splitp(p[8 * NH], p[8 * NH + 1], h1, lo1);
            splitp(p[8], p[9], h2, lo2);
            splitp(p[8 * NH + 8], p[8 * NH + 9], h3, lo3);
            const int frag = (j * 2 + kfo) * 4 + mf;
            g_hhf[0][frag * 32 + l] = make_uint4(h0, h1, h2, h3);
            g_hlf[0][frag * 32 + l] = make_uint4(lo0, lo1, lo2, lo3);
        }
        __syncthreads();
        if (tid == 0) st_rel(&g_fh[j], 0);       // h(0) published
    } else {
        __syncthreads();
    }

    const int sl = slen[m];

    if (role == 0) {
        // -------- z-gate producer --------
        const float* Xbase = g_X + ((size_t)0 * TSTEPS * BATCH + (size_t)m) * NH + gn0 + nq;
        for (int t = 0; t < TSTEPS; t++) {
            const float* Xt = Xbase + (size_t)t * BATCH * NH;
            float4 x0 = *(const float4*)Xt;
            float4 x1 = *(const float4*)(Xt + 4);
            warp_wait8(g_fh + kg * 8, t);
            gemm_stage(g_hhf[t & 1], g_hlf[t & 1], Wh, Wl, scr, wid, lane);
            __syncthreads();
            float pre[8];
            reduce_pre(scr, bia, x0, x1, m, nq, pre);
            float zv[8];
#pragma unroll
            for (int jj = 0; jj < 8; jj++) zv[jj] = 1.0f / (1.0f + expf(-pre[jj]));
            float* dst = g_z + (size_t)m * NH + gn0 + nq;
            *(float4*)dst = make_float4(zv[0], zv[1], zv[2], zv[3]);
            *(float4*)(dst + 4) = make_float4(zv[4], zv[5], zv[6], zv[7]);
            __syncthreads();
            if (tid == 0) st_rel(&g_fz[j], t + 1);
        }
    } else if (role == 1) {
        // -------- r-gate producer (publishes r*h planes) --------
        const float* Xbase = g_X + ((size_t)1 * TSTEPS * BATCH + (size_t)m) * NH + gn0 + nq;
        for (int t = 0; t < TSTEPS; t++) {
            const float* Xt = Xbase + (size_t)t * BATCH * NH;
            float4 x0 = *(const float4*)Xt;
            float4 x1 = *(const float4*)(Xt + 4);
            warp_wait8(g_fh + kg * 8, t);
            gemm_stage(g_hhf[t & 1], g_hlf[t & 1], Wh, Wl, scr, wid, lane);
            __syncthreads();
            float pre[8];
            reduce_pre(scr, bia, x0, x1, m, nq, pre);
            const float* hp = g_h32 + (size_t)m * NH + gn0 + nq;
#pragma unroll
            for (int jj = 0; jj < 8; jj++) {
                float s = 1.0f / (1.0f + expf(-pre[jj]));
                sbuf[m * 36 + nq + jj] = s * hp[jj];
            }
            __syncthreads();
            pack_planes(sbuf, g_rhhf, g_rhlf, j * 2, tid);
            __syncthreads();
            if (tid == 0) st_rel(&g_fr[j], t + 1);
        }
    } else {
        // -------- candidate + update --------
        const float* Xbase = g_X + ((size_t)2 * TSTEPS * BATCH + (size_t)m) * NH + gn0 + nq;
        for (int t = 0; t < TSTEPS; t++) {
            const float* Xt = Xbase + (size_t)t * BATCH * NH;
            float4 x0 = *(const float4*)Xt;
            float4 x1 = *(const float4*)(Xt + 4);
            warp_wait8(g_fr + kg * 8, t + 1);
            gemm_stage(g_rhhf, g_rhlf, Wh, Wl, scr, wid, lane);
            __syncthreads();
            // z ready? (usually yes — computed concurrently with r)
            if (ld_acq(&g_fz[j]) < t + 1) {
                while (ld_acq(&g_fz[j]) < t + 1) __nanosleep(20);
            }
            float pre[8];
            reduce_pre(scr, bia, x0, x1, m, nq, pre);
            const float* zp = g_z + (size_t)m * NH + gn0 + nq;
            float4 z0 = *(const float4*)zp;
            float4 z1 = *(const float4*)(zp + 4);
            float zv[8] = {z0.x, z0.y, z0.z, z0.w, z1.x, z1.y, z1.z, z1.w};
            float hn[8];
#pragma unroll
            for (int jj = 0; jj < 8; jj++) {
                float hc = tanhf(pre[jj]);
                float v = (1.0f - zv[jj]) * hreg[jj] + zv[jj] * hc;
                if (t >= sl) v = hreg[jj];
                hreg[jj] = v;
                hn[jj] = v;
                sbuf[m * 36 + nq + jj] = v;
            }
            float* hp = g_h32 + (size_t)m * NH + gn0 + nq;
            *(float4*)hp = make_float4(hn[0], hn[1], hn[2], hn[3]);
            *(float4*)(hp + 4) = make_float4(hn[4], hn[5], hn[6], hn[7]);
            float* op = out + (size_t)t * BATCH * NH + (size_t)m * NH + gn0 + nq;
            *(float4*)op = make_float4(hn[0], hn[1], hn[2], hn[3]);
            *(float4*)(op + 4) = make_float4(hn[4], hn[5], hn[6], hn[7]);
            __syncthreads();
            pack_planes(sbuf, g_hhf[(t + 1) & 1], g_hlf[(t + 1) & 1], j * 2, tid);
            __syncthreads();
            if (tid == 0) st_rel(&g_fh[j], t + 1);
        }
        if (write_last) {
            float* op = out + (size_t)TSTEPS * BATCH * NH + (size_t)m * NH + gn0 + nq;
            *(float4*)op = make_float4(hreg[0], hreg[1], hreg[2], hreg[3]);
            *(float4*)(op + 4) = make_float4(hreg[4], hreg[5], hreg[6], hreg[7]);
        }
    }
}

// ============================= launch =======================================
extern "C" void kernel_launch(void* const* d_in, const int* in_sizes, int n_in,
                              void* d_out, int out_size)
{
    const float* input = (const float*)d_in[0];
    const float* h0    = (const float*)d_in[1];
    const float* Wiz_w = (const float*)d_in[2];
    const float* Wiz_b = (const float*)d_in[3];
    const float* Wir_w = (const float*)d_in[4];
    const float* Wir_b = (const float*)d_in[5];
    const float* Wih_w = (const float*)d_in[6];
    const float* Wih_b = (const float*)d_in[7];
    const float* Whz_w = (const float*)d_in[8];
    const float* Whz_b = (const float*)d_in[9];
    const float* Whr_w = (const float*)d_in[10];
    const float* Whr_b = (const float*)d_in[11];
    const float* Whh_w = (const float*)d_in[12];
    const float* Whh_b = (const float*)d_in[13];
    const void*  lengths = d_in[14];

    cudaFuncSetAttribute(input_proj_kernel,
                         cudaFuncAttributeMaxDynamicSharedMemorySize, PA_SMEM);
    cudaFuncSetAttribute(gru_step_kernel,
                         cudaFuncAttributeMaxDynamicSharedMemorySize, PB_SMEM);

    init_misc_kernel<<<1, 32>>>();
    input_proj_kernel<<<256 * 24, 256, PA_SMEM>>>(input, Wiz_w, Wir_w, Wih_w);

    int write_last = (out_size >= TSTEPS * BATCH * NH + BATCH * NH) ? 1 : 0;
    gru_step_kernel<<<NBLK, 256, PB_SMEM>>>(
        h0, Whz_w, Whr_w, Whh_w, Whz_b, Whr_b, Whh_b,
        Wiz_b, Wir_b, Wih_b, lengths, (float*)d_out, write_last);
}